// round 14
// baseline (speedup 1.0000x reference)
#include <cuda_runtime.h>
#include <cuda_fp16.h>
#include <cstdint>

// ---------------------------------------------------------------------------
// SO2ConvolutionMoE, FP16 mma.sync, ONE persistent kernel:
//   phase 1 (minimal prefix): bucket (CTA0) || B1 mix || cvt of x seg1 slab
//   grid barrier (monotonic, replay-safe)
//   phase 2: single GEMM ticket (seg1 -> seg2 -> seg0). Last HELPERS CTAs
//            first finish remaining pre-work (B2,B0,bias,cvt seg0/seg2) --
//            hidden under the other CTAs' seg1 GEMM -- then join the ticket.
//            Tickets past the seg1 region gate on pre-work completion.
// GEMM: 128x128 CTA tiles, warp 64x32, KTILE=64, 3-stage cp.async, 2 CTAs/SM.
// ---------------------------------------------------------------------------

#define NEDGES 12288
#define NSYS   16
#define NEXP   8
#define ROWF   2432
#define HELPERS 32

__device__ __half g_B0[(size_t)NSYS * 640 * 640];     // [K][N]
__device__ __half g_B1[(size_t)NSYS * 1024 * 1024];
__device__ __half g_B2[(size_t)NSYS * 768 * 768];
__device__ float  g_bias0[NSYS * 640];
__device__ __half g_xh[(size_t)NEDGES * ROWF];
__device__ int    g_list[NSYS * NEDGES];
__device__ int    g_cnt[NSYS];

// coordination: monotonic counters (replay-safe), ticket reset pre-barrier
__device__ unsigned g_arrive  = 0;
__device__ unsigned g_release = 0;
__device__ unsigned g_ticket  = 0;
__device__ unsigned g_predone = 0;

__device__ __forceinline__ uint32_t h2_as_u32(__half2 h) {
    return *reinterpret_cast<const uint32_t*>(&h);
}

__device__ __forceinline__ void grid_barrier(int G) {
    __syncthreads();
    __threadfence();
    if (threadIdx.x == 0) {
        unsigned gen = *((volatile unsigned*)&g_release);
        if (atomicAdd(&g_arrive, 1) == (gen + 1) * (unsigned)G - 1) {
            atomicAdd(&g_release, 1);
        } else {
            while (*((volatile unsigned*)&g_release) == gen) {}
        }
        __threadfence();
    }
    __syncthreads();
}

// ---------------------------------------------------------------------------
// pre-work units
// phase 1: B1 mix (1024) + cvt seg1 (3072)
// helpers: B2 (576) + B0 (400) + bias (3) + cvt seg0 (1920) + cvt seg2 (2304)
// ---------------------------------------------------------------------------
#define NB1_M1   1024
#define N1_CVT   3072
#define NB1_TOT  (NB1_M1 + N1_CVT)

#define NH_M2    576
#define NH_M0    400
#define NH_BIAS  3
#define NH_CVT0  1920
#define NH_CVT2  2304
#define NH_TOT   (NH_M2 + NH_M0 + NH_BIAS + NH_CVT0 + NH_CVT2)

template <int MODE>
__device__ __forceinline__ void mix_body(const float* __restrict__ W,
                                         const float* sec, int bi, int tid) {
    constexpr int Kin   = (MODE == 0) ? 640 : (MODE == 1) ? 512 : 384;
    constexpr int Nw    = (MODE == 0) ? 640 : (MODE == 1) ? 1024 : 768;
    constexpr int SO2   = (MODE == 0) ? 0 : 1;
    constexpr int KTOT  = SO2 ? 2 * Kin : Kin;
    constexpr int TOTAL = KTOT * Nw;
    constexpr int N4    = Nw / 4;

    __half* Bd = (MODE == 0) ? g_B0 : (MODE == 1) ? g_B1 : g_B2;

    int idx4 = bi * 256 + tid;
    int k  = idx4 / N4;
    int jj = idx4 - k * N4;

    float sign = 1.f;
    size_t src4;
    if (!SO2 || k < Kin) {
        src4 = (size_t)k * N4 + jj;
    } else {
        int kk = k - Kin;
        int Nh4 = N4 >> 1;
        if (jj < Nh4) { src4 = (size_t)kk * N4 + Nh4 + jj; sign = -1.f; }
        else          { src4 = (size_t)kk * N4 + (jj - Nh4); }
    }

    const size_t esz4 = (size_t)Kin * N4;
    float4 w[NEXP];
#pragma unroll
    for (int e = 0; e < NEXP; e++) w[e] = ((const float4*)W)[e * esz4 + src4];

#pragma unroll
    for (int s = 0; s < NSYS; s++) {
        float4 a = make_float4(0.f, 0.f, 0.f, 0.f);
#pragma unroll
        for (int e = 0; e < NEXP; e++) {
            float c = sec[s * NEXP + e];
            a.x = fmaf(c, w[e].x, a.x); a.y = fmaf(c, w[e].y, a.y);
            a.z = fmaf(c, w[e].z, a.z); a.w = fmaf(c, w[e].w, a.w);
        }
        uint2 u;
        u.x = h2_as_u32(__floats2half2_rn(sign * a.x, sign * a.y));
        u.y = h2_as_u32(__floats2half2_rn(sign * a.z, sign * a.w));
        *reinterpret_cast<uint2*>(Bd + (size_t)s * TOTAL + (size_t)idx4 * 4) = u;
    }
}

// convert 1024 float4s of x within a column slab (compile-time constants ->
// divides become mul-shift), MLP-4
template <int SLABW, int SLAB0>
__device__ __forceinline__ void cvt_unit(const float* __restrict__ x,
                                         int unit, int tid) {
    float4 v[4];
    int dst[4];
#pragma unroll
    for (int u = 0; u < 4; u++) {
        int f = unit * 1024 + u * 256 + tid;
        int edge = f / SLABW;
        int off  = f - edge * SLABW;
        int s4   = edge * (ROWF / 4) + SLAB0 + off;
        dst[u] = s4;
        v[u] = ((const float4*)x)[s4];
    }
#pragma unroll
    for (int u = 0; u < 4; u++) {
        uint2 o;
        o.x = h2_as_u32(__floats2half2_rn(v[u].x, v[u].y));
        o.y = h2_as_u32(__floats2half2_rn(v[u].z, v[u].w));
        *reinterpret_cast<uint2*>(g_xh + (size_t)dst[u] * 4) = o;
    }
}

// ---------------------------------------------------------------------------
// GEMM building blocks (identical inner loop to R11/R12 best)
// ---------------------------------------------------------------------------
#define KTILE 64
#define SA_H 72
#define SB_H 136
#define STAGES 3
#define A_STAGE (128 * SA_H)
#define B_STAGE (KTILE * SB_H)
#define SMEM_HALVES (STAGES * (A_STAGE + B_STAGE))
#define SMEM_BYTES (SMEM_HALVES * 2 + 512)

__device__ __forceinline__ void mma_f16(float* d, const uint32_t* a, const uint32_t* b) {
    asm volatile(
        "mma.sync.aligned.m16n8k16.row.col.f32.f16.f16.f32 "
        "{%0,%1,%2,%3}, {%4,%5,%6,%7}, {%8,%9}, {%0,%1,%2,%3};\n"
        : "+f"(d[0]), "+f"(d[1]), "+f"(d[2]), "+f"(d[3])
        : "r"(a[0]), "r"(a[1]), "r"(a[2]), "r"(a[3]),
          "r"(b[0]), "r"(b[1]));
}

__device__ __forceinline__ void ldsm_x4(uint32_t* r, uint32_t saddr) {
    asm volatile("ldmatrix.sync.aligned.m8n8.x4.shared.b16 {%0,%1,%2,%3}, [%4];"
        : "=r"(r[0]), "=r"(r[1]), "=r"(r[2]), "=r"(r[3]) : "r"(saddr));
}

__device__ __forceinline__ void ldsm_x4_t(uint32_t* r, uint32_t saddr) {
    asm volatile("ldmatrix.sync.aligned.m8n8.x4.trans.shared.b16 {%0,%1,%2,%3}, [%4];"
        : "=r"(r[0]), "=r"(r[1]), "=r"(r[2]), "=r"(r[3]) : "r"(saddr));
}

__device__ __forceinline__ void cp16(void* dst, const void* src) {
    uint32_t sa = (uint32_t)__cvta_generic_to_shared(dst);
    asm volatile("cp.async.cg.shared.global [%0], [%1], 16;\n" :: "r"(sa), "l"(src));
}

__device__ __forceinline__ void cp16z(void* dst, const void* src, int sz) {
    uint32_t sa = (uint32_t)__cvta_generic_to_shared(dst);
    asm volatile("cp.async.cg.shared.global [%0], [%1], 16, %2;\n" :: "r"(sa), "l"(src), "r"(sz));
}

template <int SEG>
__device__ __forceinline__ void gemm_body(
    float* __restrict__ out, int sys, int m0, int n0, int cnt,
    __half* smh, int tid) {
    constexpr int K    = (SEG == 0) ? 640 : (SEG == 1) ? 1024 : 768;
    constexpr int XOFF = (SEG == 0) ? 0 : (SEG == 1) ? 640 : 1664;
    constexpr int KT   = K / KTILE;

    const __half* Bsys =
        ((SEG == 0) ? g_B0 : (SEG == 1) ? g_B1 : g_B2) + (size_t)sys * K * K;

    __half* sA = smh;
    __half* sB = smh + STAGES * A_STAGE;
    int*    sE = (int*)(smh + SMEM_HALVES);

    if (tid < 128) {
        int idx = m0 + tid;
        sE[tid] = (idx < cnt) ? g_list[sys * NEDGES + idx] : -1;
    }
    __syncthreads();

    auto load_tile = [&](int kt, int buf) {
        __half* aBuf = sA + buf * A_STAGE;
        __half* bBuf = sB + buf * B_STAGE;
#pragma unroll
        for (int i = 0; i < 4; i++) {
            int c = tid + i * 256;
            int row = c >> 3, cc = c & 7;
            int e = sE[row];
            const __half* src = g_xh +
                ((e >= 0) ? ((size_t)e * ROWF + XOFF) : (size_t)0) + kt * KTILE + cc * 8;
            cp16z(aBuf + row * SA_H + cc * 8, src, (e >= 0) ? 16 : 0);
        }
#pragma unroll
        for (int i = 0; i < 4; i++) {
            int c = tid + i * 256;
            int k = c >> 4, n8 = c & 15;
            const __half* src = Bsys + (size_t)(kt * KTILE + k) * K + n0 + n8 * 8;
            cp16(bBuf + k * SB_H + n8 * 8, src);
        }
        asm volatile("cp.async.commit_group;\n" ::);
    };

    const int lane = tid & 31, warp = tid >> 5;
    const int wm = warp & 1, wn = warp >> 1;
    const int gid = lane >> 2, tig = lane & 3;
    const int l15 = lane & 15, lhi = lane >> 4;

    float acc[4][4][4];
#pragma unroll
    for (int a = 0; a < 4; a++)
#pragma unroll
        for (int b = 0; b < 4; b++)
#pragma unroll
            for (int c = 0; c < 4; c++) acc[a][b][c] = 0.f;

    const uint32_t sA_u = (uint32_t)__cvta_generic_to_shared(sA);
    const uint32_t sB_u = (uint32_t)__cvta_generic_to_shared(sB);

    uint32_t aoff[4], boff[2];
#pragma unroll
    for (int mt = 0; mt < 4; mt++)
        aoff[mt] = ((wm * 64 + mt * 16 + l15) * SA_H + lhi * 8) * 2;
#pragma unroll
    for (int p = 0; p < 2; p++)
        boff[p] = (l15 * SB_H + wn * 32 + p * 16 + lhi * 8) * 2;

    load_tile(0, 0);
    load_tile(1, 1);

    for (int kt = 0; kt < KT; kt++) {
        if (kt + 1 < KT) asm volatile("cp.async.wait_group 1;\n" ::);
        else             asm volatile("cp.async.wait_group 0;\n" ::);
        __syncthreads();
        if (kt + 2 < KT) load_tile(kt + 2, (kt + 2) % STAGES);

        const int buf = kt % STAGES;
        const uint32_t aB = sA_u + buf * A_STAGE * 2;
        const uint32_t bB = sB_u + buf * B_STAGE * 2;

#pragma unroll
        for (int ks = 0; ks < 4; ks++) {
            uint32_t af[4][4], bf[4][2];
#pragma unroll
            for (int mt = 0; mt < 4; mt++)
                ldsm_x4(af[mt], aB + aoff[mt] + ks * 16 * 2);
#pragma unroll
            for (int p = 0; p < 2; p++) {
                uint32_t r[4];
                ldsm_x4_t(r, bB + boff[p] + ks * 16 * SB_H * 2);
                bf[2 * p][0] = r[0]; bf[2 * p][1] = r[1];
                bf[2 * p + 1][0] = r[2]; bf[2 * p + 1][1] = r[3];
            }
#pragma unroll
            for (int mt = 0; mt < 4; mt++)
#pragma unroll
                for (int nt = 0; nt < 4; nt++)
                    mma_f16(acc[mt][nt], af[mt], bf[nt]);
        }
    }

#pragma unroll
    for (int mt = 0; mt < 4; mt++) {
        int r0 = wm * 64 + mt * 16 + gid;
        int e0 = sE[r0], e1 = sE[r0 + 8];
#pragma unroll
        for (int nt = 0; nt < 4; nt++) {
            int col = n0 + wn * 32 + nt * 8 + tig * 2;
            float b0 = 0.f, b1 = 0.f;
            if (SEG == 0) {
                b0 = g_bias0[sys * 640 + col];
                b1 = g_bias0[sys * 640 + col + 1];
            }
            if (e0 >= 0) {
                float2 v;
                v.x = acc[mt][nt][0] + b0;
                v.y = acc[mt][nt][1] + b1;
                *(float2*)(out + (size_t)e0 * ROWF + XOFF + col) = v;
            }
            if (e1 >= 0) {
                float2 v;
                v.x = acc[mt][nt][2] + b0;
                v.y = acc[mt][nt][3] + b1;
                *(float2*)(out + (size_t)e1 * ROWF + XOFF + col) = v;
            }
        }
    }
}

// ---------------------------------------------------------------------------
__global__ __launch_bounds__(256, 2) void fused_all(
    const float* __restrict__ x, const float* __restrict__ ec,
    const int* __restrict__ eb,
    const float* __restrict__ Wm0, const float* __restrict__ bm0,
    const float* __restrict__ Wm1, const float* __restrict__ Wm2,
    float* __restrict__ out, int G) {
    const int tid = threadIdx.x;
    const int bid = blockIdx.x;

    __shared__ float sec[NSYS * NEXP];
    __shared__ int   hcnt[NSYS];
    __shared__ int   scnt[NSYS];
    __shared__ int   s_t;

    if (tid < NSYS * NEXP) sec[tid] = ec[tid];
    if (bid == 0 && tid == 0) g_ticket = 0;           // reset pre-barrier: safe
    if (bid == 0 && tid < NSYS) hcnt[tid] = 0;
    __syncthreads();

    // ------------- phase 1: minimal prefix -------------
    if (bid == 0) {
        for (int i = tid; i < NEDGES; i += 256) {
            int s = eb[i];
            int p = atomicAdd(&hcnt[s], 1);
            g_list[s * NEDGES + p] = i;
        }
        __syncthreads();
        if (tid < NSYS) g_cnt[tid] = hcnt[tid];
    } else {
        for (int b = bid - 1; b < NB1_TOT; b += G - 1) {
            if (b < NB1_M1) mix_body<1>(Wm1, sec, b, tid);
            else            cvt_unit<256, 160>(x, b - NB1_M1, tid);   // seg1 slab
        }
    }

    grid_barrier(G);
    const unsigned L = *((volatile unsigned*)&g_release);  // launch generation

    if (tid < NSYS) scnt[tid] = g_cnt[tid];
    __syncthreads();
    int total = 0;
#pragma unroll
    for (int s = 0; s < NSYS; s++) total += (scnt[s] + 127) >> 7;
    const int ngt1 = 8 * total;
    const int ngt  = 19 * total;

    extern __shared__ __half smh[];

    // ------------- helpers: finish remaining pre-work first -------------
    if (bid >= G - HELPERS) {
        for (int b = bid - (G - HELPERS); b < NH_TOT; b += HELPERS) {
            if (b < NH_M2) {
                mix_body<2>(Wm2, sec, b, tid);
            } else if (b < NH_M2 + NH_M0) {
                mix_body<0>(Wm0, sec, b - NH_M2, tid);
            } else if (b < NH_M2 + NH_M0 + NH_BIAS) {
                int j = (b - NH_M2 - NH_M0) * 256 + tid;
                if (j < 640) {
                    float w[NEXP];
#pragma unroll
                    for (int e = 0; e < NEXP; e++) w[e] = bm0[e * 640 + j];
#pragma unroll
                    for (int s = 0; s < NSYS; s++) {
                        float acc = 0.f;
#pragma unroll
                        for (int e = 0; e < NEXP; e++)
                            acc = fmaf(sec[s * NEXP + e], w[e], acc);
                        g_bias0[s * 640 + j] = acc;
                    }
                }
            } else if (b < NH_M2 + NH_M0 + NH_BIAS + NH_CVT0) {
                cvt_unit<160, 0>(x, b - NH_M2 - NH_M0 - NH_BIAS, tid);          // seg0
            } else {
                cvt_unit<192, 416>(x, b - NH_M2 - NH_M0 - NH_BIAS - NH_CVT0, tid); // seg2
            }
        }
        __syncthreads();
        __threadfence();
        if (tid == 0) atomicAdd(&g_predone, 1);
    }

    // ------------- single GEMM ticket (seg1 -> seg2 -> seg0) -------------
    bool gated = false;
    while (true) {
        __syncthreads();
        if (tid == 0) s_t = (int)atomicAdd(&g_ticket, 1);
        __syncthreads();
        int t = s_t;
        if (t >= ngt) break;

        if (t >= ngt1 && !gated) {
            // seg2/seg0 tiles need helper pre-work complete
            if (tid == 0)
                while (*((volatile unsigned*)&g_predone) < L * (unsigned)HELPERS) {}
            __syncthreads();
            gated = true;
        }

        if (t < ngt1) {
            int mt = t >> 3;
            const int n0 = (t & 7) * 128;
            int sys = 0, msv;
            while (mt >= (msv = ((scnt[sys] + 127) >> 7))) { mt -= msv; sys++; }
            gemm_body<1>(out, sys, mt << 7, n0, scnt[sys], smh, tid);
        } else if (t < 14 * total) {
            int u = t - ngt1;
            int mt = u / 6;
            const int n0 = (u - mt * 6) * 128;
            int sys = 0, msv;
            while (mt >= (msv = ((scnt[sys] + 127) >> 7))) { mt -= msv; sys++; }
            gemm_body<2>(out, sys, mt << 7, n0, scnt[sys], smh, tid);
        } else {
            int u = t - 14 * total;
            int mt = u / 5;
            const int n0 = (u - mt * 5) * 128;
            int sys = 0, msv;
            while (mt >= (msv = ((scnt[sys] + 127) >> 7))) { mt -= msv; sys++; }
            gemm_body<0>(out, sys, mt << 7, n0, scnt[sys], smh, tid);
        }
    }
}

// ---------------------------------------------------------------------------
extern "C" void kernel_launch(void* const* d_in, const int* in_sizes, int n_in,
                              void* d_out, int out_size) {
    const float* x   = (const float*)d_in[0];
    const float* ec  = (const float*)d_in[2];
    const int*   eb  = (const int*)d_in[3];
    const float* Wm0 = (const float*)d_in[4];
    const float* bm0 = (const float*)d_in[5];
    const float* Wm1 = (const float*)d_in[6];
    const float* Wm2 = (const float*)d_in[7];
    float* out = (float*)d_out;

    static int G = [] {
        int nsm = 0;
        cudaDeviceGetAttribute(&nsm, cudaDevAttrMultiProcessorCount, 0);
        cudaFuncSetAttribute(fused_all,
                             cudaFuncAttributeMaxDynamicSharedMemorySize, SMEM_BYTES);
        return nsm * 2;
    }();

    fused_all<<<G, 256, SMEM_BYTES>>>(x, ec, eb, Wm0, bm0, Wm1, Wm2, out, G);
}

// round 15
// speedup vs baseline: 1.2405x; 1.2405x over previous
#include <cuda_runtime.h>
#include <cuda_fp16.h>
#include <cstdint>

// ---------------------------------------------------------------------------
// SO2ConvolutionMoE, FP16 mma.sync, ONE persistent kernel:
//   phase 1 (minimal prefix): bucket (CTA0) || B1 mix || cvt x seg1 slab
//   grid barrier
//   phase 2: ALL CTAs alternate pre-chunk tickets (B2,B0,bias,cvt seg0/seg2;
//            full-grid bandwidth) with GEMM tile tickets (seg1->seg2->seg0).
//            First seg2/seg0 tile gates on pre completion (monotonic counter).
// GEMM: 128x128 CTA tiles, warp 64x32, KTILE=64, 3-stage cp.async, 2 CTAs/SM.
// ---------------------------------------------------------------------------

#define NEDGES 12288
#define NSYS   16
#define NEXP   8
#define ROWF   2432

__device__ __half g_B0[(size_t)NSYS * 640 * 640];     // [K][N]
__device__ __half g_B1[(size_t)NSYS * 1024 * 1024];
__device__ __half g_B2[(size_t)NSYS * 768 * 768];
__device__ float  g_bias0[NSYS * 640];
__device__ __half g_xh[(size_t)NEDGES * ROWF];
__device__ int    g_list[NSYS * NEDGES];
__device__ int    g_cnt[NSYS];

// coordination: barrier/gate counters monotonic (replay-safe);
// tickets reset pre-barrier by CTA0.
__device__ unsigned g_arrive  = 0;
__device__ unsigned g_release = 0;
__device__ unsigned g_ticket  = 0;
__device__ unsigned g_tpre    = 0;
__device__ unsigned g_predone = 0;

__device__ __forceinline__ uint32_t h2_as_u32(__half2 h) {
    return *reinterpret_cast<const uint32_t*>(&h);
}

__device__ __forceinline__ void grid_barrier(int G) {
    __syncthreads();
    __threadfence();
    if (threadIdx.x == 0) {
        unsigned gen = *((volatile unsigned*)&g_release);
        if (atomicAdd(&g_arrive, 1) == (gen + 1) * (unsigned)G - 1) {
            atomicAdd(&g_release, 1);
        } else {
            while (*((volatile unsigned*)&g_release) == gen) {}
        }
        __threadfence();
    }
    __syncthreads();
}

// ---------------------------------------------------------------------------
// pre-work units
// phase 1: B1 mix (1024) + cvt seg1 (3072)
// phase 2: B2 (576) + B0 (400) + bias (3) + cvt seg0 (1920) + cvt seg2 (2304)
// ---------------------------------------------------------------------------
#define NB1_M1   1024
#define N1_CVT   3072
#define NB1_TOT  (NB1_M1 + N1_CVT)

#define NH_M2    576
#define NH_M0    400
#define NH_BIAS  3
#define NH_CVT0  1920
#define NH_CVT2  2304
#define NH_TOT   (NH_M2 + NH_M0 + NH_BIAS + NH_CVT0 + NH_CVT2)   // 5203
#define CHUNK    8
#define NPRE_CHUNKS ((NH_TOT + CHUNK - 1) / CHUNK)               // 651

template <int MODE>
__device__ __forceinline__ void mix_body(const float* __restrict__ W,
                                         const float* sec, int bi, int tid) {
    constexpr int Kin   = (MODE == 0) ? 640 : (MODE == 1) ? 512 : 384;
    constexpr int Nw    = (MODE == 0) ? 640 : (MODE == 1) ? 1024 : 768;
    constexpr int SO2   = (MODE == 0) ? 0 : 1;
    constexpr int KTOT  = SO2 ? 2 * Kin : Kin;
    constexpr int TOTAL = KTOT * Nw;
    constexpr int N4    = Nw / 4;

    __half* Bd = (MODE == 0) ? g_B0 : (MODE == 1) ? g_B1 : g_B2;

    int idx4 = bi * 256 + tid;
    int k  = idx4 / N4;
    int jj = idx4 - k * N4;

    float sign = 1.f;
    size_t src4;
    if (!SO2 || k < Kin) {
        src4 = (size_t)k * N4 + jj;
    } else {
        int kk = k - Kin;
        int Nh4 = N4 >> 1;
        if (jj < Nh4) { src4 = (size_t)kk * N4 + Nh4 + jj; sign = -1.f; }
        else          { src4 = (size_t)kk * N4 + (jj - Nh4); }
    }

    const size_t esz4 = (size_t)Kin * N4;
    float4 w[NEXP];
#pragma unroll
    for (int e = 0; e < NEXP; e++) w[e] = ((const float4*)W)[e * esz4 + src4];

#pragma unroll
    for (int s = 0; s < NSYS; s++) {
        float4 a = make_float4(0.f, 0.f, 0.f, 0.f);
#pragma unroll
        for (int e = 0; e < NEXP; e++) {
            float c = sec[s * NEXP + e];
            a.x = fmaf(c, w[e].x, a.x); a.y = fmaf(c, w[e].y, a.y);
            a.z = fmaf(c, w[e].z, a.z); a.w = fmaf(c, w[e].w, a.w);
        }
        uint2 u;
        u.x = h2_as_u32(__floats2half2_rn(sign * a.x, sign * a.y));
        u.y = h2_as_u32(__floats2half2_rn(sign * a.z, sign * a.w));
        *reinterpret_cast<uint2*>(Bd + (size_t)s * TOTAL + (size_t)idx4 * 4) = u;
    }
}

// convert 1024 float4s of x within a column slab (compile-time consts), MLP-4
template <int SLABW, int SLAB0>
__device__ __forceinline__ void cvt_unit(const float* __restrict__ x,
                                         int unit, int tid) {
    float4 v[4];
    int dst[4];
#pragma unroll
    for (int u = 0; u < 4; u++) {
        int f = unit * 1024 + u * 256 + tid;
        int edge = f / SLABW;
        int off  = f - edge * SLABW;
        int s4   = edge * (ROWF / 4) + SLAB0 + off;
        dst[u] = s4;
        v[u] = ((const float4*)x)[s4];
    }
#pragma unroll
    for (int u = 0; u < 4; u++) {
        uint2 o;
        o.x = h2_as_u32(__floats2half2_rn(v[u].x, v[u].y));
        o.y = h2_as_u32(__floats2half2_rn(v[u].z, v[u].w));
        *reinterpret_cast<uint2*>(g_xh + (size_t)dst[u] * 4) = o;
    }
}

__device__ __forceinline__ void pre_unit(
    int b, int tid, const float* __restrict__ x, const float* sec,
    const float* __restrict__ Wm0, const float* __restrict__ bm0,
    const float* __restrict__ Wm2) {
    if (b < NH_M2) {
        mix_body<2>(Wm2, sec, b, tid);
    } else if (b < NH_M2 + NH_M0) {
        mix_body<0>(Wm0, sec, b - NH_M2, tid);
    } else if (b < NH_M2 + NH_M0 + NH_BIAS) {
        int j = (b - NH_M2 - NH_M0) * 256 + tid;
        if (j < 640) {
            float w[NEXP];
#pragma unroll
            for (int e = 0; e < NEXP; e++) w[e] = bm0[e * 640 + j];
#pragma unroll
            for (int s = 0; s < NSYS; s++) {
                float acc = 0.f;
#pragma unroll
                for (int e = 0; e < NEXP; e++)
                    acc = fmaf(sec[s * NEXP + e], w[e], acc);
                g_bias0[s * 640 + j] = acc;
            }
        }
    } else if (b < NH_M2 + NH_M0 + NH_BIAS + NH_CVT0) {
        cvt_unit<160, 0>(x, b - NH_M2 - NH_M0 - NH_BIAS, tid);               // seg0
    } else {
        cvt_unit<192, 416>(x, b - NH_M2 - NH_M0 - NH_BIAS - NH_CVT0, tid);   // seg2
    }
}

// ---------------------------------------------------------------------------
// GEMM building blocks (identical inner loop to R11/R12 best)
// ---------------------------------------------------------------------------
#define KTILE 64
#define SA_H 72
#define SB_H 136
#define STAGES 3
#define A_STAGE (128 * SA_H)
#define B_STAGE (KTILE * SB_H)
#define SMEM_HALVES (STAGES * (A_STAGE + B_STAGE))
#define SMEM_BYTES (SMEM_HALVES * 2 + 512)

__device__ __forceinline__ void mma_f16(float* d, const uint32_t* a, const uint32_t* b) {
    asm volatile(
        "mma.sync.aligned.m16n8k16.row.col.f32.f16.f16.f32 "
        "{%0,%1,%2,%3}, {%4,%5,%6,%7}, {%8,%9}, {%0,%1,%2,%3};\n"
        : "+f"(d[0]), "+f"(d[1]), "+f"(d[2]), "+f"(d[3])
        : "r"(a[0]), "r"(a[1]), "r"(a[2]), "r"(a[3]),
          "r"(b[0]), "r"(b[1]));
}

__device__ __forceinline__ void ldsm_x4(uint32_t* r, uint32_t saddr) {
    asm volatile("ldmatrix.sync.aligned.m8n8.x4.shared.b16 {%0,%1,%2,%3}, [%4];"
        : "=r"(r[0]), "=r"(r[1]), "=r"(r[2]), "=r"(r[3]) : "r"(saddr));
}

__device__ __forceinline__ void ldsm_x4_t(uint32_t* r, uint32_t saddr) {
    asm volatile("ldmatrix.sync.aligned.m8n8.x4.trans.shared.b16 {%0,%1,%2,%3}, [%4];"
        : "=r"(r[0]), "=r"(r[1]), "=r"(r[2]), "=r"(r[3]) : "r"(saddr));
}

__device__ __forceinline__ void cp16(void* dst, const void* src) {
    uint32_t sa = (uint32_t)__cvta_generic_to_shared(dst);
    asm volatile("cp.async.cg.shared.global [%0], [%1], 16;\n" :: "r"(sa), "l"(src));
}

__device__ __forceinline__ void cp16z(void* dst, const void* src, int sz) {
    uint32_t sa = (uint32_t)__cvta_generic_to_shared(dst);
    asm volatile("cp.async.cg.shared.global [%0], [%1], 16, %2;\n" :: "r"(sa), "l"(src), "r"(sz));
}

template <int SEG>
__device__ __forceinline__ void gemm_body(
    float* __restrict__ out, int sys, int m0, int n0, int cnt,
    __half* smh, int tid) {
    constexpr int K    = (SEG == 0) ? 640 : (SEG == 1) ? 1024 : 768;
    constexpr int XOFF = (SEG == 0) ? 0 : (SEG == 1) ? 640 : 1664;
    constexpr int KT   = K / KTILE;

    const __half* Bsys =
        ((SEG == 0) ? g_B0 : (SEG == 1) ? g_B1 : g_B2) + (size_t)sys * K * K;

    __half* sA = smh;
    __half* sB = smh + STAGES * A_STAGE;
    int*    sE = (int*)(smh + SMEM_HALVES);

    if (tid < 128) {
        int idx = m0 + tid;
        sE[tid] = (idx < cnt) ? g_list[sys * NEDGES + idx] : -1;
    }
    __syncthreads();

    auto load_tile = [&](int kt, int buf) {
        __half* aBuf = sA + buf * A_STAGE;
        __half* bBuf = sB + buf * B_STAGE;
#pragma unroll
        for (int i = 0; i < 4; i++) {
            int c = tid + i * 256;
            int row = c >> 3, cc = c & 7;
            int e = sE[row];
            const __half* src = g_xh +
                ((e >= 0) ? ((size_t)e * ROWF + XOFF) : (size_t)0) + kt * KTILE + cc * 8;
            cp16z(aBuf + row * SA_H + cc * 8, src, (e >= 0) ? 16 : 0);
        }
#pragma unroll
        for (int i = 0; i < 4; i++) {
            int c = tid + i * 256;
            int k = c >> 4, n8 = c & 15;
            const __half* src = Bsys + (size_t)(kt * KTILE + k) * K + n0 + n8 * 8;
            cp16(bBuf + k * SB_H + n8 * 8, src);
        }
        asm volatile("cp.async.commit_group;\n" ::);
    };

    const int lane = tid & 31, warp = tid >> 5;
    const int wm = warp & 1, wn = warp >> 1;
    const int gid = lane >> 2, tig = lane & 3;
    const int l15 = lane & 15, lhi = lane >> 4;

    float acc[4][4][4];
#pragma unroll
    for (int a = 0; a < 4; a++)
#pragma unroll
        for (int b = 0; b < 4; b++)
#pragma unroll
            for (int c = 0; c < 4; c++) acc[a][b][c] = 0.f;

    const uint32_t sA_u = (uint32_t)__cvta_generic_to_shared(sA);
    const uint32_t sB_u = (uint32_t)__cvta_generic_to_shared(sB);

    uint32_t aoff[4], boff[2];
#pragma unroll
    for (int mt = 0; mt < 4; mt++)
        aoff[mt] = ((wm * 64 + mt * 16 + l15) * SA_H + lhi * 8) * 2;
#pragma unroll
    for (int p = 0; p < 2; p++)
        boff[p] = (l15 * SB_H + wn * 32 + p * 16 + lhi * 8) * 2;

    load_tile(0, 0);
    load_tile(1, 1);

    for (int kt = 0; kt < KT; kt++) {
        if (kt + 1 < KT) asm volatile("cp.async.wait_group 1;\n" ::);
        else             asm volatile("cp.async.wait_group 0;\n" ::);
        __syncthreads();
        if (kt + 2 < KT) load_tile(kt + 2, (kt + 2) % STAGES);

        const int buf = kt % STAGES;
        const uint32_t aB = sA_u + buf * A_STAGE * 2;
        const uint32_t bB = sB_u + buf * B_STAGE * 2;

#pragma unroll
        for (int ks = 0; ks < 4; ks++) {
            uint32_t af[4][4], bf[4][2];
#pragma unroll
            for (int mt = 0; mt < 4; mt++)
                ldsm_x4(af[mt], aB + aoff[mt] + ks * 16 * 2);
#pragma unroll
            for (int p = 0; p < 2; p++) {
                uint32_t r[4];
                ldsm_x4_t(r, bB + boff[p] + ks * 16 * SB_H * 2);
                bf[2 * p][0] = r[0]; bf[2 * p][1] = r[1];
                bf[2 * p + 1][0] = r[2]; bf[2 * p + 1][1] = r[3];
            }
#pragma unroll
            for (int mt = 0; mt < 4; mt++)
#pragma unroll
                for (int nt = 0; nt < 4; nt++)
                    mma_f16(acc[mt][nt], af[mt], bf[nt]);
        }
    }

#pragma unroll
    for (int mt = 0; mt < 4; mt++) {
        int r0 = wm * 64 + mt * 16 + gid;
        int e0 = sE[r0], e1 = sE[r0 + 8];
#pragma unroll
        for (int nt = 0; nt < 4; nt++) {
            int col = n0 + wn * 32 + nt * 8 + tig * 2;
            float b0 = 0.f, b1 = 0.f;
            if (SEG == 0) {
                b0 = g_bias0[sys * 640 + col];
                b1 = g_bias0[sys * 640 + col + 1];
            }
            if (e0 >= 0) {
                float2 v;
                v.x = acc[mt][nt][0] + b0;
                v.y = acc[mt][nt][1] + b1;
                *(float2*)(out + (size_t)e0 * ROWF + XOFF + col) = v;
            }
            if (e1 >= 0) {
                float2 v;
                v.x = acc[mt][nt][2] + b0;
                v.y = acc[mt][nt][3] + b1;
                *(float2*)(out + (size_t)e1 * ROWF + XOFF + col) = v;
            }
        }
    }
}

// ---------------------------------------------------------------------------
__global__ __launch_bounds__(256, 2) void fused_all(
    const float* __restrict__ x, const float* __restrict__ ec,
    const int* __restrict__ eb,
    const float* __restrict__ Wm0, const float* __restrict__ bm0,
    const float* __restrict__ Wm1, const float* __restrict__ Wm2,
    float* __restrict__ out, int G) {
    const int tid = threadIdx.x;
    const int bid = blockIdx.x;

    __shared__ float sec[NSYS * NEXP];
    __shared__ int   hcnt[NSYS];
    __shared__ int   scnt[NSYS];
    __shared__ int   s_t, s_p;

    if (tid < NSYS * NEXP) sec[tid] = ec[tid];
    if (bid == 0 && tid == 0) { g_ticket = 0; g_tpre = 0; }   // pre-barrier reset
    if (bid == 0 && tid < NSYS) hcnt[tid] = 0;
    __syncthreads();

    // ------------- phase 1: minimal prefix -------------
    if (bid == 0) {
        for (int i = tid; i < NEDGES; i += 256) {
            int s = eb[i];
            int p = atomicAdd(&hcnt[s], 1);
            g_list[s * NEDGES + p] = i;
        }
        __syncthreads();
        if (tid < NSYS) g_cnt[tid] = hcnt[tid];
    } else {
        for (int b = bid - 1; b < NB1_TOT; b += G - 1) {
            if (b < NB1_M1) mix_body<1>(Wm1, sec, b, tid);
            else            cvt_unit<256, 160>(x, b - NB1_M1, tid);   // seg1 slab
        }
    }

    grid_barrier(G);
    const unsigned L = *((volatile unsigned*)&g_release);   // launch generation

    if (tid < NSYS) scnt[tid] = g_cnt[tid];
    __syncthreads();
    int total = 0;
#pragma unroll
    for (int s = 0; s < NSYS; s++) total += (scnt[s] + 127) >> 7;
    const int ngt1 = 8 * total;
    const int ngt  = 19 * total;

    extern __shared__ __half smh[];

    // ------------- phase 2: interleaved pre chunks + GEMM tickets -------------
    bool more_pre = true;
    bool gated = false;
    while (true) {
        // one pre chunk (all CTAs participate -> full-grid bandwidth)
        if (more_pre) {
            __syncthreads();
            if (tid == 0) s_p = (int)atomicAdd(&g_tpre, 1);
            __syncthreads();
            int p = s_p;
            if (p >= NPRE_CHUNKS) {
                more_pre = false;
            } else {
                int b0 = p * CHUNK;
                int b1 = (b0 + CHUNK < NH_TOT) ? b0 + CHUNK : NH_TOT;
                for (int b = b0; b < b1; b++)
                    pre_unit(b, tid, x, sec, Wm0, bm0, Wm2);
                __threadfence();
                __syncthreads();
                if (tid == 0) atomicAdd(&g_predone, 1);
            }
        }

        // one GEMM tile
        __syncthreads();
        if (tid == 0) s_t = (int)atomicAdd(&g_ticket, 1);
        __syncthreads();
        int t = s_t;
        if (t >= ngt) {
            if (!more_pre) break;
            continue;                       // keep draining pre chunks
        }

        if (t >= ngt1 && !gated) {
            if (tid == 0)
                while (*((volatile unsigned*)&g_predone) <
                       L * (unsigned)NPRE_CHUNKS) {}
            __syncthreads();
            __threadfence();
            gated = true;
        }

        if (t < ngt1) {
            int mt = t >> 3;
            const int n0 = (t & 7) * 128;
            int sys = 0, msv;
            while (mt >= (msv = ((scnt[sys] + 127) >> 7))) { mt -= msv; sys++; }
            gemm_body<1>(out, sys, mt << 7, n0, scnt[sys], smh, tid);
        } else if (t < 14 * total) {
            int u = t - ngt1;
            int mt = u / 6;
            const int n0 = (u - mt * 6) * 128;
            int sys = 0, msv;
            while (mt >= (msv = ((scnt[sys] + 127) >> 7))) { mt -= msv; sys++; }
            gemm_body<2>(out, sys, mt << 7, n0, scnt[sys], smh, tid);
        } else {
            int u = t - 14 * total;
            int mt = u / 5;
            const int n0 = (u - mt * 5) * 128;
            int sys = 0, msv;
            while (mt >= (msv = ((scnt[sys] + 127) >> 7))) { mt -= msv; sys++; }
            gemm_body<0>(out, sys, mt << 7, n0, scnt[sys], smh, tid);
        }
    }
}

// ---------------------------------------------------------------------------
extern "C" void kernel_launch(void* const* d_in, const int* in_sizes, int n_in,
                              void* d_out, int out_size) {
    const float* x   = (const float*)d_in[0];
    const float* ec  = (const float*)d_in[2];
    const int*   eb  = (const int*)d_in[3];
    const float* Wm0 = (const float*)d_in[4];
    const float* bm0 = (const float*)d_in[5];
    const float* Wm1 = (const float*)d_in[6];
    const float* Wm2 = (const float*)d_in[7];
    float* out = (float*)d_out;

    static int G = [] {
        int nsm = 0;
        cudaDeviceGetAttribute(&nsm, cudaDevAttrMultiProcessorCount, 0);
        cudaFuncSetAttribute(fused_all,
                             cudaFuncAttributeMaxDynamicSharedMemorySize, SMEM_BYTES);
        return nsm * 2;
    }();

    fused_all<<<G, 256, SMEM_BYTES>>>(x, ec, eb, Wm0, bm0, Wm1, Wm2, out, G);
}

// round 16
// speedup vs baseline: 1.2671x; 1.0214x over previous
#include <cuda_runtime.h>
#include <cuda_fp16.h>
#include <cstdint>

// ---------------------------------------------------------------------------
// SO2ConvolutionMoE, FP16 mma.sync, ONE persistent kernel (R12 architecture):
//   phase 1: CTA0 buckets edges; other CTAs do weight mixes + bias + x->fp16
//   grid barrier (monotonic, replay-safe)
//   phase 2: GEMM tiles via atomic ticket (seg1 -> seg2 -> seg0).
//            NEW: next tile's ticket + edge list + 2-stage prologue are issued
//            BEFORE the current tile's epilogue (loads hidden under stores).
// GEMM: 128x128 CTA tiles, warp 64x32, KTILE=64, 3-stage cp.async, 2 CTAs/SM.
// ---------------------------------------------------------------------------

#define NEDGES 12288
#define NSYS   16
#define NEXP   8
#define ROWF   2432

__device__ __half g_B0[(size_t)NSYS * 640 * 640];     // [K][N]
__device__ __half g_B1[(size_t)NSYS * 1024 * 1024];
__device__ __half g_B2[(size_t)NSYS * 768 * 768];
__device__ float  g_bias0[NSYS * 640];
__device__ __half g_xh[(size_t)NEDGES * ROWF];
__device__ int    g_list[NSYS * NEDGES];
__device__ int    g_cnt[NSYS];

__device__ unsigned g_arrive  = 0;
__device__ unsigned g_release = 0;
__device__ unsigned g_ticket  = 0;

__device__ __forceinline__ uint32_t h2_as_u32(__half2 h) {
    return *reinterpret_cast<const uint32_t*>(&h);
}

__device__ __forceinline__ void grid_barrier(int G) {
    __syncthreads();
    __threadfence();
    if (threadIdx.x == 0) {
        unsigned gen = *((volatile unsigned*)&g_release);
        if (atomicAdd(&g_arrive, 1) == (gen + 1) * (unsigned)G - 1) {
            atomicAdd(&g_release, 1);
        } else {
            while (*((volatile unsigned*)&g_release) == gen) {}
        }
        __threadfence();
    }
    __syncthreads();
}

// ---------------------------------------------------------------------------
// pre-phase work units (same distribution as R12: whole grid, full bandwidth)
// ---------------------------------------------------------------------------
#define NB_BIAS 3
#define NB_M1   1024
#define NB_M2   576
#define NB_M0   400
#define NB_REST (NB_BIAS + NB_M1 + NB_M2 + NB_M0)
#define T4_CVT  (NEDGES * ROWF / 4)

template <int MODE>
__device__ __forceinline__ void mix_body(const float* __restrict__ W,
                                         const float* sec, int bi, int tid) {
    constexpr int Kin   = (MODE == 0) ? 640 : (MODE == 1) ? 512 : 384;
    constexpr int Nw    = (MODE == 0) ? 640 : (MODE == 1) ? 1024 : 768;
    constexpr int SO2   = (MODE == 0) ? 0 : 1;
    constexpr int KTOT  = SO2 ? 2 * Kin : Kin;
    constexpr int TOTAL = KTOT * Nw;
    constexpr int N4    = Nw / 4;

    __half* Bd = (MODE == 0) ? g_B0 : (MODE == 1) ? g_B1 : g_B2;

    int idx4 = bi * 256 + tid;
    if (idx4 >= TOTAL / 4) return;
    int k  = idx4 / N4;
    int jj = idx4 - k * N4;

    float sign = 1.f;
    size_t src4;
    if (!SO2 || k < Kin) {
        src4 = (size_t)k * N4 + jj;
    } else {
        int kk = k - Kin;
        int Nh4 = N4 >> 1;
        if (jj < Nh4) { src4 = (size_t)kk * N4 + Nh4 + jj; sign = -1.f; }
        else          { src4 = (size_t)kk * N4 + (jj - Nh4); }
    }

    const size_t esz4 = (size_t)Kin * N4;
    float4 w[NEXP];
#pragma unroll
    for (int e = 0; e < NEXP; e++) w[e] = ((const float4*)W)[e * esz4 + src4];

#pragma unroll
    for (int s = 0; s < NSYS; s++) {
        float4 a = make_float4(0.f, 0.f, 0.f, 0.f);
#pragma unroll
        for (int e = 0; e < NEXP; e++) {
            float c = sec[s * NEXP + e];
            a.x = fmaf(c, w[e].x, a.x); a.y = fmaf(c, w[e].y, a.y);
            a.z = fmaf(c, w[e].z, a.z); a.w = fmaf(c, w[e].w, a.w);
        }
        uint2 u;
        u.x = h2_as_u32(__floats2half2_rn(sign * a.x, sign * a.y));
        u.y = h2_as_u32(__floats2half2_rn(sign * a.z, sign * a.w));
        *reinterpret_cast<uint2*>(Bd + (size_t)s * TOTAL + (size_t)idx4 * 4) = u;
    }
}

// ---------------------------------------------------------------------------
// GEMM building blocks
// ---------------------------------------------------------------------------
#define KTILE 64
#define SA_H 72
#define SB_H 136
#define STAGES 3
#define A_STAGE (128 * SA_H)
#define B_STAGE (KTILE * SB_H)
#define SMEM_HALVES (STAGES * (A_STAGE + B_STAGE))
#define SMEM_BYTES (SMEM_HALVES * 2 + 2048)

__device__ __forceinline__ void mma_f16(float* d, const uint32_t* a, const uint32_t* b) {
    asm volatile(
        "mma.sync.aligned.m16n8k16.row.col.f32.f16.f16.f32 "
        "{%0,%1,%2,%3}, {%4,%5,%6,%7}, {%8,%9}, {%0,%1,%2,%3};\n"
        : "+f"(d[0]), "+f"(d[1]), "+f"(d[2]), "+f"(d[3])
        : "r"(a[0]), "r"(a[1]), "r"(a[2]), "r"(a[3]),
          "r"(b[0]), "r"(b[1]));
}

__device__ __forceinline__ void ldsm_x4(uint32_t* r, uint32_t saddr) {
    asm volatile("ldmatrix.sync.aligned.m8n8.x4.shared.b16 {%0,%1,%2,%3}, [%4];"
        : "=r"(r[0]), "=r"(r[1]), "=r"(r[2]), "=r"(r[3]) : "r"(saddr));
}

__device__ __forceinline__ void ldsm_x4_t(uint32_t* r, uint32_t saddr) {
    asm volatile("ldmatrix.sync.aligned.m8n8.x4.trans.shared.b16 {%0,%1,%2,%3}, [%4];"
        : "=r"(r[0]), "=r"(r[1]), "=r"(r[2]), "=r"(r[3]) : "r"(saddr));
}

__device__ __forceinline__ void cp16(void* dst, const void* src) {
    uint32_t sa = (uint32_t)__cvta_generic_to_shared(dst);
    asm volatile("cp.async.cg.shared.global [%0], [%1], 16;\n" :: "r"(sa), "l"(src));
}

__device__ __forceinline__ void cp16z(void* dst, const void* src, int sz) {
    uint32_t sa = (uint32_t)__cvta_generic_to_shared(dst);
    asm volatile("cp.async.cg.shared.global [%0], [%1], 16, %2;\n" :: "r"(sa), "l"(src), "r"(sz));
}

__device__ __forceinline__ int seg_K(int seg)    { return seg == 0 ? 640 : (seg == 1 ? 1024 : 768); }
__device__ __forceinline__ int seg_XOFF(int seg) { return seg == 0 ? 0   : (seg == 1 ? 640  : 1664); }
__device__ __forceinline__ const __half* seg_B(int seg) {
    return seg == 0 ? g_B0 : (seg == 1 ? g_B1 : g_B2);
}

__device__ __forceinline__ void decode_tile(int t, const int* scnt, int total,
                                            int& seg, int& sys, int& m0,
                                            int& n0, int& cnt) {
    int nbs;
    if (t < 8 * total) { seg = 1; nbs = 8; }
    else {
        t -= 8 * total;
        if (t < 6 * total) { seg = 2; nbs = 6; }
        else { t -= 6 * total; seg = 0; nbs = 5; }
    }
    int mt = t / nbs;
    n0 = (t - mt * nbs) * 128;
    sys = 0;
    int msv;
    while (mt >= (msv = ((scnt[sys] + 127) >> 7))) { mt -= msv; sys++; }
    m0 = mt << 7;
    cnt = scnt[sys];
}

// runtime-seg tile loader (prologue only; geometry identical across segs)
__device__ __forceinline__ void load_tile_rt(
    int kt, int buf, const int* sE, int XOFF, int K, const __half* Bsys,
    int n0, __half* smh, int tid) {
    __half* aBuf = smh + buf * A_STAGE;
    __half* bBuf = smh + STAGES * A_STAGE + buf * B_STAGE;
#pragma unroll
    for (int i = 0; i < 4; i++) {
        int c = tid + i * 256;
        int row = c >> 3, cc = c & 7;
        int e = sE[row];
        const __half* src = g_xh +
            ((e >= 0) ? ((size_t)e * ROWF + XOFF) : (size_t)0) + kt * KTILE + cc * 8;
        cp16z(aBuf + row * SA_H + cc * 8, src, (e >= 0) ? 16 : 0);
    }
#pragma unroll
    for (int i = 0; i < 4; i++) {
        int c = tid + i * 256;
        int k = c >> 4, n8 = c & 15;
        const __half* src = Bsys + (size_t)(kt * KTILE + k) * K + n0 + n8 * 8;
        cp16(bBuf + k * SB_H + n8 * 8, src);
    }
    asm volatile("cp.async.commit_group;\n" ::);
}

// One tile: mainloop (stages 0,1 preloaded) -> prefetch next tile -> epilogue.
// Returns the next ticket.
template <int SEG>
__device__ int gemm_tile(
    float* __restrict__ out, int sys, int m0, int n0, int cnt,
    const int* sE, int* sE_nxt, __half* smh, int tid,
    const int* scnt, int total, int ngt, int* s_t_ptr) {
    constexpr int K    = (SEG == 0) ? 640 : (SEG == 1) ? 1024 : 768;
    constexpr int XOFF = (SEG == 0) ? 0 : (SEG == 1) ? 640 : 1664;
    constexpr int KT   = K / KTILE;

    const __half* Bsys =
        ((SEG == 0) ? g_B0 : (SEG == 1) ? g_B1 : g_B2) + (size_t)sys * K * K;

    __half* sA = smh;
    __half* sB = smh + STAGES * A_STAGE;

    auto load_tile = [&](int kt, int buf) {
        __half* aBuf = sA + buf * A_STAGE;
        __half* bBuf = sB + buf * B_STAGE;
#pragma unroll
        for (int i = 0; i < 4; i++) {
            int c = tid + i * 256;
            int row = c >> 3, cc = c & 7;
            int e = sE[row];
            const __half* src = g_xh +
                ((e >= 0) ? ((size_t)e * ROWF + XOFF) : (size_t)0) + kt * KTILE + cc * 8;
            cp16z(aBuf + row * SA_H + cc * 8, src, (e >= 0) ? 16 : 0);
        }
#pragma unroll
        for (int i = 0; i < 4; i++) {
            int c = tid + i * 256;
            int k = c >> 4, n8 = c & 15;
            const __half* src = Bsys + (size_t)(kt * KTILE + k) * K + n0 + n8 * 8;
            cp16(bBuf + k * SB_H + n8 * 8, src);
        }
        asm volatile("cp.async.commit_group;\n" ::);
    };

    const int lane = tid & 31, warp = tid >> 5;
    const int wm = warp & 1, wn = warp >> 1;
    const int gid = lane >> 2, tig = lane & 3;
    const int l15 = lane & 15, lhi = lane >> 4;

    float acc[4][4][4];
#pragma unroll
    for (int a = 0; a < 4; a++)
#pragma unroll
        for (int b = 0; b < 4; b++)
#pragma unroll
            for (int c = 0; c < 4; c++) acc[a][b][c] = 0.f;

    const uint32_t sA_u = (uint32_t)__cvta_generic_to_shared(sA);
    const uint32_t sB_u = (uint32_t)__cvta_generic_to_shared(sB);

    uint32_t aoff[4], boff[2];
#pragma unroll
    for (int mt = 0; mt < 4; mt++)
        aoff[mt] = ((wm * 64 + mt * 16 + l15) * SA_H + lhi * 8) * 2;
#pragma unroll
    for (int p = 0; p < 2; p++)
        boff[p] = (l15 * SB_H + wn * 32 + p * 16 + lhi * 8) * 2;

    // mainloop (stages 0,1 already in flight from the prologue)
    for (int kt = 0; kt < KT; kt++) {
        if (kt + 1 < KT) asm volatile("cp.async.wait_group 1;\n" ::);
        else             asm volatile("cp.async.wait_group 0;\n" ::);
        __syncthreads();
        if (kt + 2 < KT) load_tile(kt + 2, (kt + 2) % STAGES);

        const int buf = kt % STAGES;
        const uint32_t aB = sA_u + buf * A_STAGE * 2;
        const uint32_t bB = sB_u + buf * B_STAGE * 2;

#pragma unroll
        for (int ks = 0; ks < 4; ks++) {
            uint32_t af[4][4], bf[4][2];
#pragma unroll
            for (int mt = 0; mt < 4; mt++)
                ldsm_x4(af[mt], aB + aoff[mt] + ks * 16 * 2);
#pragma unroll
            for (int p = 0; p < 2; p++) {
                uint32_t r[4];
                ldsm_x4_t(r, bB + boff[p] + ks * 16 * SB_H * 2);
                bf[2 * p][0] = r[0]; bf[2 * p][1] = r[1];
                bf[2 * p + 1][0] = r[2]; bf[2 * p + 1][1] = r[3];
            }
#pragma unroll
            for (int mt = 0; mt < 4; mt++)
#pragma unroll
                for (int nt = 0; nt < 4; nt++)
                    mma_f16(acc[mt][nt], af[mt], bf[nt]);
        }
    }

    // --- prefetch next tile BEFORE the epilogue ---
    if (tid == 0) *s_t_ptr = (int)atomicAdd(&g_ticket, 1);
    __syncthreads();                       // stage reuse safety + s_t visible
    int tn = *s_t_ptr;
    if (tn < ngt) {
        int nseg, nsys, nm0, nn0, ncnt;
        decode_tile(tn, scnt, total, nseg, nsys, nm0, nn0, ncnt);
        if (tid < 128) {
            int idx = nm0 + tid;
            sE_nxt[tid] = (idx < ncnt) ? g_list[nsys * NEDGES + idx] : -1;
        }
        __syncthreads();
        int nK = seg_K(nseg);
        const __half* nB = seg_B(nseg) + (size_t)nsys * nK * nK;
        int nX = seg_XOFF(nseg);
        load_tile_rt(0, 0, sE_nxt, nX, nK, nB, nn0, smh, tid);
        load_tile_rt(1, 1, sE_nxt, nX, nK, nB, nn0, smh, tid);
    }

    // --- epilogue (overlaps with next tile's cp.async) ---
#pragma unroll
    for (int mt = 0; mt < 4; mt++) {
        int r0 = wm * 64 + mt * 16 + gid;
        int e0 = sE[r0], e1 = sE[r0 + 8];
#pragma unroll
        for (int nt = 0; nt < 4; nt++) {
            int col = n0 + wn * 32 + nt * 8 + tig * 2;
            float b0 = 0.f, b1 = 0.f;
            if (SEG == 0) {
                b0 = g_bias0[sys * 640 + col];
                b1 = g_bias0[sys * 640 + col + 1];
            }
            if (e0 >= 0) {
                float2 v;
                v.x = acc[mt][nt][0] + b0;
                v.y = acc[mt][nt][1] + b1;
                *(float2*)(out + (size_t)e0 * ROWF + XOFF + col) = v;
            }
            if (e1 >= 0) {
                float2 v;
                v.x = acc[mt][nt][2] + b0;
                v.y = acc[mt][nt][3] + b1;
                *(float2*)(out + (size_t)e1 * ROWF + XOFF + col) = v;
            }
        }
    }
    return tn;
}

// ---------------------------------------------------------------------------
__global__ __launch_bounds__(256, 2) void fused_all(
    const float* __restrict__ x, const float* __restrict__ ec,
    const int* __restrict__ eb,
    const float* __restrict__ Wm0, const float* __restrict__ bm0,
    const float* __restrict__ Wm1, const float* __restrict__ Wm2,
    float* __restrict__ out, int G) {
    const int tid = threadIdx.x;
    const int bid = blockIdx.x;

    __shared__ float sec[NSYS * NEXP];
    __shared__ int   hcnt[NSYS];
    __shared__ int   scnt[NSYS];
    __shared__ int   s_t;

    if (tid < NSYS * NEXP) sec[tid] = ec[tid];
    if (bid == 0 && tid == 0) g_ticket = 0;          // pre-barrier reset: safe
    if (bid == 0 && tid < NSYS) hcnt[tid] = 0;
    __syncthreads();

    // ---------------- phase 1: preprocessing (R12 layout) ----------------
    if (bid == 0) {
        for (int i = tid; i < NEDGES; i += 256) {
            int s = eb[i];
            int p = atomicAdd(&hcnt[s], 1);
            g_list[s * NEDGES + p] = i;
        }
        __syncthreads();
        if (tid < NSYS) g_cnt[tid] = hcnt[tid];
    } else {
        for (int b = bid - 1; b < NB_REST; b += G - 1) {
            if (b < NB_BIAS) {
                int j = b * 256 + tid;
                if (j < 640) {
                    float w[NEXP];
#pragma unroll
                    for (int e = 0; e < NEXP; e++) w[e] = bm0[e * 640 + j];
#pragma unroll
                    for (int s = 0; s < NSYS; s++) {
                        float acc = 0.f;
#pragma unroll
                        for (int e = 0; e < NEXP; e++)
                            acc = fmaf(sec[s * NEXP + e], w[e], acc);
                        g_bias0[s * 640 + j] = acc;
                    }
                }
            } else if (b < NB_BIAS + NB_M1) {
                mix_body<1>(Wm1, sec, b - NB_BIAS, tid);
            } else if (b < NB_BIAS + NB_M1 + NB_M2) {
                mix_body<2>(Wm2, sec, b - NB_BIAS - NB_M1, tid);
            } else {
                mix_body<0>(Wm0, sec, b - NB_BIAS - NB_M1 - NB_M2, tid);
            }
        }
        // cvt x fp32 -> fp16, MLP-4
        for (int base = (bid - 1) * 1024; base < T4_CVT; base += (G - 1) * 1024) {
            float4 v[4];
#pragma unroll
            for (int u = 0; u < 4; u++)
                v[u] = ((const float4*)x)[base + u * 256 + tid];
#pragma unroll
            for (int u = 0; u < 4; u++) {
                uint2 o;
                o.x = h2_as_u32(__floats2half2_rn(v[u].x, v[u].y));
                o.y = h2_as_u32(__floats2half2_rn(v[u].z, v[u].w));
                *reinterpret_cast<uint2*>(g_xh + (size_t)(base + u * 256 + tid) * 4) = o;
            }
        }
    }

    grid_barrier(G);

    // ---------------- phase 2: GEMM via ticket with prefetch ----------------
    if (tid < NSYS) scnt[tid] = g_cnt[tid];
    __syncthreads();
    int total = 0;
#pragma unroll
    for (int s = 0; s < NSYS; s++) total += (scnt[s] + 127) >> 7;
    const int ngt = 19 * total;

    extern __shared__ __half smh[];
    int* sEb = (int*)(smh + SMEM_HALVES);     // two 128-entry edge-list buffers

    // first ticket + prologue
    if (tid == 0) s_t = (int)atomicAdd(&g_ticket, 1);
    __syncthreads();
    int t = s_t;
    int cur = 0;
    if (t < ngt) {
        int seg, sys, m0, n0, cnt;
        decode_tile(t, scnt, total, seg, sys, m0, n0, cnt);
        if (tid < 128) {
            int idx = m0 + tid;
            sEb[tid] = (idx < cnt) ? g_list[sys * NEDGES + idx] : -1;
        }
        __syncthreads();
        int K = seg_K(seg);
        const __half* Bs = seg_B(seg) + (size_t)sys * K * K;
        int X = seg_XOFF(seg);
        load_tile_rt(0, 0, sEb, X, K, Bs, n0, smh, tid);
        load_tile_rt(1, 1, sEb, X, K, Bs, n0, smh, tid);
    }

    while (t < ngt) {
        int seg, sys, m0, n0, cnt;
        decode_tile(t, scnt, total, seg, sys, m0, n0, cnt);
        int* sE_cur = sEb + cur * 128;
        int* sE_nxt = sEb + (cur ^ 1) * 128;
        int tn;
        if (seg == 1)
            tn = gemm_tile<1>(out, sys, m0, n0, cnt, sE_cur, sE_nxt, smh, tid,
                              scnt, total, ngt, &s_t);
        else if (seg == 2)
            tn = gemm_tile<2>(out, sys, m0, n0, cnt, sE_cur, sE_nxt, smh, tid,
                              scnt, total, ngt, &s_t);
        else
            tn = gemm_tile<0>(out, sys, m0, n0, cnt, sE_cur, sE_nxt, smh, tid,
                              scnt, total, ngt, &s_t);
        t = tn;
        cur ^= 1;
    }
}

// ---------------------------------------------------------------------------
extern "C" void kernel_launch(void* const* d_in, const int* in_sizes, int n_in,
                              void* d_out, int out_size) {
    const float* x   = (const float*)d_in[0];
    const float* ec  = (const float*)d_in[2];
    const int*   eb  = (const int*)d_in[3];
    const float* Wm0 = (const float*)d_in[4];
    const float* bm0 = (const float*)d_in[5];
    const float* Wm1 = (const float*)d_in[6];
    const float* Wm2 = (const float*)d_in[7];
    float* out = (float*)d_out;

    static int G = [] {
        int nsm = 0;
        cudaDeviceGetAttribute(&nsm, cudaDevAttrMultiProcessorCount, 0);
        cudaFuncSetAttribute(fused_all,
                             cudaFuncAttributeMaxDynamicSharedMemorySize, SMEM_BYTES);
        return nsm * 2;
    }();

    fused_all<<<G, 256, SMEM_BYTES>>>(x, ec, eb, Wm0, bm0, Wm1, Wm2, out, G);
}

// round 17
// speedup vs baseline: 1.3204x; 1.0421x over previous
#include <cuda_runtime.h>
#include <cuda_fp16.h>
#include <cstdint>

// ---------------------------------------------------------------------------
// SO2ConvolutionMoE, FP16 mma.sync, ONE persistent kernel (R12 architecture):
//   phase 1: CTA0 buckets edges (smem histogram); other CTAs do weight mixes
//            (SO(2) recombined, fp16) + bias + x->fp16 (MLP-4 cvt loop)
//   grid barrier (monotonic, replay-safe)
//   phase 2: GEMM tiles pulled via atomic ticket; 128x128 CTA tiles,
//            warp 64x32 (2M x 4N), KTILE=64, 3-stage cp.async, 2 CTAs/SM.
//   R17 delta vs R12: kt mainloop NOT unrolled (#pragma unroll 1) to keep the
//   SASS footprint inside L1.5 I$; monotonic grid barrier.
// ---------------------------------------------------------------------------

#define NEDGES 12288
#define NSYS   16
#define NEXP   8
#define ROWF   2432

__device__ __half g_B0[(size_t)NSYS * 640 * 640];     // [K][N]
__device__ __half g_B1[(size_t)NSYS * 1024 * 1024];
__device__ __half g_B2[(size_t)NSYS * 768 * 768];
__device__ float  g_bias0[NSYS * 640];
__device__ __half g_xh[(size_t)NEDGES * ROWF];
__device__ int    g_list[NSYS * NEDGES];
__device__ int    g_cnt[NSYS];

// coordination: monotonic barrier counters (replay-safe); ticket reset pre-barrier
__device__ unsigned g_arrive  = 0;
__device__ unsigned g_release = 0;
__device__ unsigned g_ticket  = 0;

__device__ __forceinline__ uint32_t h2_as_u32(__half2 h) {
    return *reinterpret_cast<const uint32_t*>(&h);
}

__device__ __forceinline__ void grid_barrier(int G) {
    __syncthreads();
    __threadfence();
    if (threadIdx.x == 0) {
        unsigned gen = *((volatile unsigned*)&g_release);
        if (atomicAdd(&g_arrive, 1) == (gen + 1) * (unsigned)G - 1) {
            atomicAdd(&g_release, 1);
        } else {
            while (*((volatile unsigned*)&g_release) == gen) {}
        }
        __threadfence();
    }
    __syncthreads();
}

// ---------------------------------------------------------------------------
// pre-phase work units (whole grid, full DRAM bandwidth -- proven R12 layout)
// ---------------------------------------------------------------------------
#define NB_BIAS 3
#define NB_M1   1024     // (1024*1024/4)/256
#define NB_M2   576      // (768*768/4)/256
#define NB_M0   400      // (640*640/4)/256
#define NB_REST (NB_BIAS + NB_M1 + NB_M2 + NB_M0)
#define T4_CVT  (NEDGES * ROWF / 4)      // 7,471,104 float4s (multiple of 1024)

template <int MODE>
__device__ __forceinline__ void mix_body(const float* __restrict__ W,
                                         const float* sec, int bi, int tid) {
    constexpr int Kin   = (MODE == 0) ? 640 : (MODE == 1) ? 512 : 384;
    constexpr int Nw    = (MODE == 0) ? 640 : (MODE == 1) ? 1024 : 768;
    constexpr int SO2   = (MODE == 0) ? 0 : 1;
    constexpr int KTOT  = SO2 ? 2 * Kin : Kin;
    constexpr int TOTAL = KTOT * Nw;
    constexpr int N4    = Nw / 4;

    __half* Bd = (MODE == 0) ? g_B0 : (MODE == 1) ? g_B1 : g_B2;

    int idx4 = bi * 256 + tid;
    if (idx4 >= TOTAL / 4) return;
    int k  = idx4 / N4;
    int jj = idx4 - k * N4;

    float sign = 1.f;
    size_t src4;
    if (!SO2 || k < Kin) {
        src4 = (size_t)k * N4 + jj;
    } else {
        int kk = k - Kin;
        int Nh4 = N4 >> 1;
        if (jj < Nh4) { src4 = (size_t)kk * N4 + Nh4 + jj; sign = -1.f; }
        else          { src4 = (size_t)kk * N4 + (jj - Nh4); }
    }

    const size_t esz4 = (size_t)Kin * N4;
    float4 w[NEXP];
#pragma unroll
    for (int e = 0; e < NEXP; e++) w[e] = ((const float4*)W)[e * esz4 + src4];

#pragma unroll
    for (int s = 0; s < NSYS; s++) {
        float4 a = make_float4(0.f, 0.f, 0.f, 0.f);
#pragma unroll
        for (int e = 0; e < NEXP; e++) {
            float c = sec[s * NEXP + e];
            a.x = fmaf(c, w[e].x, a.x); a.y = fmaf(c, w[e].y, a.y);
            a.z = fmaf(c, w[e].z, a.z); a.w = fmaf(c, w[e].w, a.w);
        }
        uint2 u;
        u.x = h2_as_u32(__floats2half2_rn(sign * a.x, sign * a.y));
        u.y = h2_as_u32(__floats2half2_rn(sign * a.z, sign * a.w));
        *reinterpret_cast<uint2*>(Bd + (size_t)s * TOTAL + (size_t)idx4 * 4) = u;
    }
}

// ---------------------------------------------------------------------------
// GEMM building blocks (R12-identical inner loop; kt loop kept rolled)
// ---------------------------------------------------------------------------
#define KTILE 64
#define SA_H 72
#define SB_H 136
#define STAGES 3
#define A_STAGE (128 * SA_H)
#define B_STAGE (KTILE * SB_H)
#define SMEM_HALVES (STAGES * (A_STAGE + B_STAGE))
#define SMEM_BYTES (SMEM_HALVES * 2 + 512)

__device__ __forceinline__ void mma_f16(float* d, const uint32_t* a, const uint32_t* b) {
    asm volatile(
        "mma.sync.aligned.m16n8k16.row.col.f32.f16.f16.f32 "
        "{%0,%1,%2,%3}, {%4,%5,%6,%7}, {%8,%9}, {%0,%1,%2,%3};\n"
        : "+f"(d[0]), "+f"(d[1]), "+f"(d[2]), "+f"(d[3])
        : "r"(a[0]), "r"(a[1]), "r"(a[2]), "r"(a[3]),
          "r"(b[0]), "r"(b[1]));
}

__device__ __forceinline__ void ldsm_x4(uint32_t* r, uint32_t saddr) {
    asm volatile("ldmatrix.sync.aligned.m8n8.x4.shared.b16 {%0,%1,%2,%3}, [%4];"
        : "=r"(r[0]), "=r"(r[1]), "=r"(r[2]), "=r"(r[3]) : "r"(saddr));
}

__device__ __forceinline__ void ldsm_x4_t(uint32_t* r, uint32_t saddr) {
    asm volatile("ldmatrix.sync.aligned.m8n8.x4.trans.shared.b16 {%0,%1,%2,%3}, [%4];"
        : "=r"(r[0]), "=r"(r[1]), "=r"(r[2]), "=r"(r[3]) : "r"(saddr));
}

__device__ __forceinline__ void cp16(void* dst, const void* src) {
    uint32_t sa = (uint32_t)__cvta_generic_to_shared(dst);
    asm volatile("cp.async.cg.shared.global [%0], [%1], 16;\n" :: "r"(sa), "l"(src));
}

__device__ __forceinline__ void cp16z(void* dst, const void* src, int sz) {
    uint32_t sa = (uint32_t)__cvta_generic_to_shared(dst);
    asm volatile("cp.async.cg.shared.global [%0], [%1], 16, %2;\n" :: "r"(sa), "l"(src), "r"(sz));
}

template <int SEG>
__device__ __forceinline__ void gemm_body(
    float* __restrict__ out, int sys, int m0, int n0, int cnt,
    __half* smh, int tid) {
    constexpr int K    = (SEG == 0) ? 640 : (SEG == 1) ? 1024 : 768;
    constexpr int XOFF = (SEG == 0) ? 0 : (SEG == 1) ? 640 : 1664;
    constexpr int KT   = K / KTILE;

    const __half* Bsys =
        ((SEG == 0) ? g_B0 : (SEG == 1) ? g_B1 : g_B2) + (size_t)sys * K * K;

    __half* sA = smh;
    __half* sB = smh + STAGES * A_STAGE;
    int*    sE = (int*)(smh + SMEM_HALVES);

    if (tid < 128) {
        int idx = m0 + tid;
        sE[tid] = (idx < cnt) ? g_list[sys * NEDGES + idx] : -1;
    }
    __syncthreads();

    auto load_tile = [&](int kt, int buf) {
        __half* aBuf = sA + buf * A_STAGE;
        __half* bBuf = sB + buf * B_STAGE;
#pragma unroll
        for (int i = 0; i < 4; i++) {
            int c = tid + i * 256;
            int row = c >> 3, cc = c & 7;
            int e = sE[row];
            const __half* src = g_xh +
                ((e >= 0) ? ((size_t)e * ROWF + XOFF) : (size_t)0) + kt * KTILE + cc * 8;
            cp16z(aBuf + row * SA_H + cc * 8, src, (e >= 0) ? 16 : 0);
        }
#pragma unroll
        for (int i = 0; i < 4; i++) {
            int c = tid + i * 256;
            int k = c >> 4, n8 = c & 15;
            const __half* src = Bsys + (size_t)(kt * KTILE + k) * K + n0 + n8 * 8;
            cp16(bBuf + k * SB_H + n8 * 8, src);
        }
        asm volatile("cp.async.commit_group;\n" ::);
    };

    const int lane = tid & 31, warp = tid >> 5;
    const int wm = warp & 1, wn = warp >> 1;
    const int gid = lane >> 2, tig = lane & 3;
    const int l15 = lane & 15, lhi = lane >> 4;

    float acc[4][4][4];
#pragma unroll
    for (int a = 0; a < 4; a++)
#pragma unroll
        for (int b = 0; b < 4; b++)
#pragma unroll
            for (int c = 0; c < 4; c++) acc[a][b][c] = 0.f;

    const uint32_t sA_u = (uint32_t)__cvta_generic_to_shared(sA);
    const uint32_t sB_u = (uint32_t)__cvta_generic_to_shared(sB);

    uint32_t aoff[4], boff[2];
#pragma unroll
    for (int mt = 0; mt < 4; mt++)
        aoff[mt] = ((wm * 64 + mt * 16 + l15) * SA_H + lhi * 8) * 2;
#pragma unroll
    for (int p = 0; p < 2; p++)
        boff[p] = (l15 * SB_H + wn * 32 + p * 16 + lhi * 8) * 2;

    load_tile(0, 0);
    load_tile(1, 1);

    // rolled mainloop: keeps the SASS body ~1 iteration in I$ (3 SEG bodies
    // would otherwise unroll to ~60-100KB each and thrash L1.5 I$).
#pragma unroll 1
    for (int kt = 0; kt < KT; kt++) {
        if (kt + 1 < KT) asm volatile("cp.async.wait_group 1;\n" ::);
        else             asm volatile("cp.async.wait_group 0;\n" ::);
        __syncthreads();
        if (kt + 2 < KT) load_tile(kt + 2, (kt + 2) % STAGES);

        const int buf = kt % STAGES;
        const uint32_t aB = sA_u + buf * A_STAGE * 2;
        const uint32_t bB = sB_u + buf * B_STAGE * 2;

#pragma unroll
        for (int ks = 0; ks < 4; ks++) {
            uint32_t af[4][4], bf[4][2];
#pragma unroll
            for (int mt = 0; mt < 4; mt++)
                ldsm_x4(af[mt], aB + aoff[mt] + ks * 16 * 2);
#pragma unroll
            for (int p = 0; p < 2; p++) {
                uint32_t r[4];
                ldsm_x4_t(r, bB + boff[p] + ks * 16 * SB_H * 2);
                bf[2 * p][0] = r[0]; bf[2 * p][1] = r[1];
                bf[2 * p + 1][0] = r[2]; bf[2 * p + 1][1] = r[3];
            }
#pragma unroll
            for (int mt = 0; mt < 4; mt++)
#pragma unroll
                for (int nt = 0; nt < 4; nt++)
                    mma_f16(acc[mt][nt], af[mt], bf[nt]);
        }
    }

    // epilogue: scatter rows by edge id, fold bias for seg 0
#pragma unroll
    for (int mt = 0; mt < 4; mt++) {
        int r0 = wm * 64 + mt * 16 + gid;
        int e0 = sE[r0], e1 = sE[r0 + 8];
#pragma unroll
        for (int nt = 0; nt < 4; nt++) {
            int col = n0 + wn * 32 + nt * 8 + tig * 2;
            float b0 = 0.f, b1 = 0.f;
            if (SEG == 0) {
                b0 = g_bias0[sys * 640 + col];
                b1 = g_bias0[sys * 640 + col + 1];
            }
            if (e0 >= 0) {
                float2 v;
                v.x = acc[mt][nt][0] + b0;
                v.y = acc[mt][nt][1] + b1;
                *(float2*)(out + (size_t)e0 * ROWF + XOFF + col) = v;
            }
            if (e1 >= 0) {
                float2 v;
                v.x = acc[mt][nt][2] + b0;
                v.y = acc[mt][nt][3] + b1;
                *(float2*)(out + (size_t)e1 * ROWF + XOFF + col) = v;
            }
        }
    }
}

// ---------------------------------------------------------------------------
__global__ __launch_bounds__(256, 2) void fused_all(
    const float* __restrict__ x, const float* __restrict__ ec,
    const int* __restrict__ eb,
    const float* __restrict__ Wm0, const float* __restrict__ bm0,
    const float* __restrict__ Wm1, const float* __restrict__ Wm2,
    float* __restrict__ out, int G) {
    const int tid = threadIdx.x;
    const int bid = blockIdx.x;

    __shared__ float sec[NSYS * NEXP];
    __shared__ int   hcnt[NSYS];
    __shared__ int   scnt[NSYS];
    __shared__ int   s_t;

    if (tid < NSYS * NEXP) sec[tid] = ec[tid];
    if (bid == 0 && tid == 0) g_ticket = 0;
    if (bid == 0 && tid < NSYS) hcnt[tid] = 0;
    __syncthreads();

    // ---------------- phase 1: preprocessing ----------------
    if (bid == 0) {
        for (int i = tid; i < NEDGES; i += 256) {
            int s = eb[i];
            int p = atomicAdd(&hcnt[s], 1);
            g_list[s * NEDGES + p] = i;
        }
        __syncthreads();
        if (tid < NSYS) g_cnt[tid] = hcnt[tid];
    } else {
#pragma unroll 1
        for (int b = bid - 1; b < NB_REST; b += G - 1) {
            if (b < NB_BIAS) {
                int j = b * 256 + tid;
                if (j < 640) {
                    float w[NEXP];
#pragma unroll
                    for (int e = 0; e < NEXP; e++) w[e] = bm0[e * 640 + j];
#pragma unroll
                    for (int s = 0; s < NSYS; s++) {
                        float acc = 0.f;
#pragma unroll
                        for (int e = 0; e < NEXP; e++)
                            acc = fmaf(sec[s * NEXP + e], w[e], acc);
                        g_bias0[s * 640 + j] = acc;
                    }
                }
            } else if (b < NB_BIAS + NB_M1) {
                mix_body<1>(Wm1, sec, b - NB_BIAS, tid);
            } else if (b < NB_BIAS + NB_M1 + NB_M2) {
                mix_body<2>(Wm2, sec, b - NB_BIAS - NB_M1, tid);
            } else {
                mix_body<0>(Wm0, sec, b - NB_BIAS - NB_M1 - NB_M2, tid);
            }
        }
        // cvt x fp32 -> fp16, 4 independent float4s in flight (MLP 4)
#pragma unroll 1
        for (int base = (bid - 1) * 1024; base < T4_CVT; base += (G - 1) * 1024) {
            float4 v[4];
#pragma unroll
            for (int u = 0; u < 4; u++)
                v[u] = ((const float4*)x)[base + u * 256 + tid];
#pragma unroll
            for (int u = 0; u < 4; u++) {
                uint2 o;
                o.x = h2_as_u32(__floats2half2_rn(v[u].x, v[u].y));
                o.y = h2_as_u32(__floats2half2_rn(v[u].z, v[u].w));
                *reinterpret_cast<uint2*>(g_xh + (size_t)(base + u * 256 + tid) * 4) = o;
            }
        }
    }

    // ---------------- grid barrier ----------------
    grid_barrier(G);

    // ---------------- phase 2: GEMM via ticket ----------------
    if (tid < NSYS) scnt[tid] = g_cnt[tid];
    __syncthreads();
    int total = 0;
#pragma unroll
    for (int s = 0; s < NSYS; s++) total += (scnt[s] + 127) >> 7;
    const int ngt = 19 * total;

    extern __shared__ __half smh[];

#pragma unroll 1
    while (true) {
        __syncthreads();                     // protect s_t + smem reuse
        if (tid == 0) s_t = (int)atomicAdd(&g_ticket, 1);
        __syncthreads();
        int t = s_t;
        if (t >= ngt) break;

        int seg, nbs_;
        if (t < 8 * total) { seg = 1; nbs_ = 8; }
        else {
            t -= 8 * total;
            if (t < 6 * total) { seg = 2; nbs_ = 6; }
            else { t -= 6 * total; seg = 0; nbs_ = 5; }
        }
        int mt = t / nbs_;
        const int n0 = (t - mt * nbs_) * 128;
        int sys = 0, msv;
        while (mt >= (msv = ((scnt[sys] + 127) >> 7))) { mt -= msv; sys++; }
        const int m0  = mt << 7;
        const int cnt = scnt[sys];

        if (seg == 1)      gemm_body<1>(out, sys, m0, n0, cnt, smh, tid);
        else if (seg == 2) gemm_body<2>(out, sys, m0, n0, cnt, smh, tid);
        else               gemm_body<0>(out, sys, m0, n0, cnt, smh, tid);
    }
}

// ---------------------------------------------------------------------------
extern "C" void kernel_launch(void* const* d_in, const int* in_sizes, int n_in,
                              void* d_out, int out_size) {
    const float* x   = (const float*)d_in[0];
    const float* ec  = (const float*)d_in[2];
    const int*   eb  = (const int*)d_in[3];
    const float* Wm0 = (const float*)d_in[4];
    const float* bm0 = (const float*)d_in[5];
    const float* Wm1 = (const float*)d_in[6];
    const float* Wm2 = (const float*)d_in[7];
    float* out = (float*)d_out;

    static int G = [] {
        int nsm = 0;
        cudaDeviceGetAttribute(&nsm, cudaDevAttrMultiProcessorCount, 0);
        cudaFuncSetAttribute(fused_all,
                             cudaFuncAttributeMaxDynamicSharedMemorySize, SMEM_BYTES);
        return nsm * 2;
    }();

    fused_all<<<G, 256, SMEM_BYTES>>>(x, ec, eb, Wm0, bm0, Wm1, Wm2, out, G);
}